// round 2
// baseline (speedup 1.0000x reference)
#include <cuda_runtime.h>
#include <math.h>
#include <stdint.h>

// Problem constants
#define BATCH   512
#define CH      256
#define CLS     60
#define MEMSZ   684
#define BR      41040   // MEMSZ * CLS
#define POSN    128
#define NEGN    512

// ------------------------- device scratch (no allocations allowed) ----------
__device__ float  g_pairs[(size_t)BATCH * BR];   // 84 MB all_pairs
__device__ float  g_pos[BATCH * POSN];
__device__ float  g_Eh[BATCH];
__device__ float  g_Er[BATCH];
__device__ int    g_colmap[BR];
__device__ double g_loss;

// ------------------------- small init kernels -------------------------------
__global__ void init_loss_kernel() { g_loss = 0.0; }

__global__ void colmap_init_kernel() {
    int j = blockIdx.x * blockDim.x + threadIdx.x;
    if (j < BR) g_colmap[j] = -1;
}

__global__ void colmap_scatter_kernel(const int* __restrict__ eidx) {
    int m = threadIdx.x + blockIdx.x * blockDim.x;
    if (m < BATCH) g_colmap[eidx[m]] = m;
}

// ------------------------- GEMM: P = F @ bank^T -----------------------------
// M=BATCH(512), N=BR(41040), K=CH(256). 64x64 tiles, 256 threads, 4x4/thread.
__global__ __launch_bounds__(256) void gemm_kernel(const float* __restrict__ F,
                                                   const float* __restrict__ B) {
    __shared__ float As[64][33];
    __shared__ float Bs[64][33];
    const int bj = blockIdx.x * 64;   // bank-row base
    const int bn = blockIdx.y * 64;   // batch base
    const int tid = threadIdx.x;
    const int tx = tid & 15;          // 16 cols of threads
    const int ty = tid >> 4;          // 16 rows of threads
    float acc[4][4] = {};

    for (int k0 = 0; k0 < CH; k0 += 32) {
#pragma unroll
        for (int l = 0; l < 2; l++) {
            int idx = tid + l * 256;       // 0..511 float4 slots
            int r = idx >> 3;              // row 0..63
            int c = (idx & 7) << 2;        // col 0,4,..28
            float4 v = *(const float4*)&F[(size_t)(bn + r) * CH + k0 + c];
            As[r][c] = v.x; As[r][c + 1] = v.y; As[r][c + 2] = v.z; As[r][c + 3] = v.w;
            int jr = bj + r;
            float4 w = make_float4(0.f, 0.f, 0.f, 0.f);
            if (jr < BR) w = *(const float4*)&B[(size_t)jr * CH + k0 + c];
            Bs[r][c] = w.x; Bs[r][c + 1] = w.y; Bs[r][c + 2] = w.z; Bs[r][c + 3] = w.w;
        }
        __syncthreads();
#pragma unroll
        for (int kk = 0; kk < 32; kk++) {
            float a[4], b[4];
#pragma unroll
            for (int i = 0; i < 4; i++) a[i] = As[ty * 4 + i][kk];
#pragma unroll
            for (int j = 0; j < 4; j++) b[j] = Bs[tx * 4 + j][kk];
#pragma unroll
            for (int i = 0; i < 4; i++)
#pragma unroll
                for (int j = 0; j < 4; j++) acc[i][j] += a[i] * b[j];
        }
        __syncthreads();
    }
#pragma unroll
    for (int i = 0; i < 4; i++) {
        int n = bn + ty * 4 + i;
#pragma unroll
        for (int j = 0; j < 4; j++) {
            int col = bj + tx * 4 + j;
            if (col < BR) g_pairs[(size_t)n * BR + col] = acc[i][j];
        }
    }
}

// ------------------------- fixup: enqueued columns = F @ f_m ----------------
__global__ void fixup_kernel(const float* __restrict__ F, const int* __restrict__ eidx) {
    int m = blockIdx.x;               // 0..511
    __shared__ float fm[CH];
    for (int k = threadIdx.x; k < CH; k += blockDim.x) fm[k] = F[(size_t)m * CH + k];
    __syncthreads();
    int col = eidx[m];
    for (int n = threadIdx.x; n < BATCH; n += blockDim.x) {
        const float* fn = &F[(size_t)n * CH];
        float s = 0.f;
#pragma unroll 8
        for (int k = 0; k < CH; k++) s += fn[k] * fm[k];
        g_pairs[(size_t)n * BR + col] = s;
    }
}

// ------------------------- positives: 128 smallest of 684 -------------------
__global__ __launch_bounds__(256) void pos_kernel(const int* __restrict__ label,
                                                  const float* __restrict__ flag) {
    int n = blockIdx.x;
    __shared__ float v[1024];
    int lbl = label[n];
    const float* row = g_pairs + (size_t)n * BR;
    for (int t = threadIdx.x; t < 1024; t += blockDim.x) {
        float x = INFINITY;
        if (t < MEMSZ) {
            int col = lbl + CLS * t;
            if (flag[col] > 0.f || g_colmap[col] >= 0) x = row[col];
        }
        v[t] = x;
    }
    __syncthreads();
    // bitonic sort ascending, 1024 elements
    for (int k = 2; k <= 1024; k <<= 1) {
        for (int j2 = k >> 1; j2 > 0; j2 >>= 1) {
            for (int i = threadIdx.x; i < 1024; i += blockDim.x) {
                int ixj = i ^ j2;
                if (ixj > i) {
                    bool up = ((i & k) == 0);
                    float a = v[i], b = v[ixj];
                    if (up ? (a > b) : (a < b)) { v[i] = b; v[ixj] = a; }
                }
            }
            __syncthreads();
        }
    }
    for (int t = threadIdx.x; t < POSN; t += blockDim.x) g_pos[n * POSN + t] = v[t];
}

// ------------------------- deterministic block reduce -----------------------
__device__ __forceinline__ float blockReduceSum(float v, float* warpBuf) {
#pragma unroll
    for (int o = 16; o > 0; o >>= 1) v += __shfl_down_sync(0xffffffffu, v, o);
    int lane = threadIdx.x & 31, w = threadIdx.x >> 5;
    if (lane == 0) warpBuf[w] = v;
    __syncthreads();
    float s = 0.f;
    if (threadIdx.x == 0) {
        int nw = blockDim.x >> 5;
        for (int i = 0; i < nw; i++) s += warpBuf[i];
    }
    __syncthreads();
    return s;   // valid on thread 0 only
}

// ------------------------- neg_hard: sum exp(top-512 largest) ---------------
#define NB  4096
#define CAP 2048

__global__ __launch_bounds__(512) void neghard_kernel(const int* __restrict__ label,
                                                      const float* __restrict__ flag) {
    __shared__ int   hist[NB];
    __shared__ float list[CAP];
    __shared__ int   s_cnt, s_B, s_cntAbove, s_need, s_done;
    __shared__ float s_lo, s_hi, s_total;
    __shared__ float warpBuf[16];

    const int n = blockIdx.x;
    const int lbl = label[n];
    const float* row = g_pairs + (size_t)n * BR;
    const int tid = threadIdx.x, nt = blockDim.x;

    if (tid == 0) { s_total = 0.f; s_lo = -1.01f; s_hi = 1.01f; s_need = NEGN; s_done = 0; }
    __syncthreads();

    for (int iter = 0; iter < 6; ++iter) {
        if (s_done) break;
        const float lo = s_lo, hi = s_hi;
        const float scale = (float)NB / (hi - lo);
        for (int b = tid; b < NB; b += nt) hist[b] = 0;
        if (tid == 0) s_cnt = 0;
        __syncthreads();
        for (int j = tid; j < BR; j += nt) {
            if ((j % CLS) != lbl && (flag[j] > 0.f || g_colmap[j] >= 0)) {
                float val = row[j];
                if (val >= lo && val < hi) {
                    int b = (int)((val - lo) * scale);
                    b = b < 0 ? 0 : (b >= NB ? NB - 1 : b);
                    atomicAdd(&hist[b], 1);
                }
            }
        }
        __syncthreads();
        if (tid == 0) {
            int need = s_need, acc = 0, B = 0;
            for (int b = NB - 1; b >= 0; b--) {
                if (acc + hist[b] >= need) { B = b; break; }
                acc += hist[b];
            }
            s_B = B; s_cntAbove = acc;
        }
        __syncthreads();
        const int B = s_B;
        const float binLo = lo + (float)B * (hi - lo) / NB;
        const float binHi = lo + (float)(B + 1) * (hi - lo) / NB;

        float myExp = 0.f;
        for (int j = tid; j < BR; j += nt) {
            if ((j % CLS) != lbl && (flag[j] > 0.f || g_colmap[j] >= 0)) {
                float val = row[j];
                if (val >= lo && val < hi) {
                    int b = (int)((val - lo) * scale);
                    b = b < 0 ? 0 : (b >= NB ? NB - 1 : b);
                    if (b > B) myExp += expf(val);
                    else if (b == B) {
                        int p = atomicAdd(&s_cnt, 1);
                        if (p < CAP) list[p] = val;
                    }
                }
            }
        }
        __syncthreads();
        float red = blockReduceSum(myExp, warpBuf);
        if (tid == 0) s_total += red;
        __syncthreads();

        const int cnt = s_cnt;
        const int need2 = s_need - s_cntAbove;
        if (cnt <= need2) {                 // take everything in the bin
            float e = 0.f;
            int lim = cnt < CAP ? cnt : CAP;
            for (int p = tid; p < lim; p += nt) e += expf(list[p]);
            float r2 = blockReduceSum(e, warpBuf);
            if (tid == 0) { s_total += r2; s_done = 1; }
            __syncthreads();
        } else if (cnt <= CAP) {            // sort descending, take first need2
            int L = 2; while (L < cnt) L <<= 1;
            for (int p = tid; p < L; p += nt) if (p >= cnt) list[p] = -INFINITY;
            __syncthreads();
            for (int k = 2; k <= L; k <<= 1)
                for (int j2 = k >> 1; j2 > 0; j2 >>= 1) {
                    for (int i = tid; i < L; i += nt) {
                        int ixj = i ^ j2;
                        if (ixj > i) {
                            bool up = ((i & k) == 0);
                            float a = list[i], b = list[ixj];
                            if (up ? (a < b) : (a > b)) { list[i] = b; list[ixj] = a; }
                        }
                    }
                    __syncthreads();
                }
            float e = 0.f;
            for (int p = tid; p < need2; p += nt) e += expf(list[p]);
            float r2 = blockReduceSum(e, warpBuf);
            if (tid == 0) { s_total += r2; s_done = 1; }
            __syncthreads();
        } else {                            // refine into boundary bin
            if (tid == 0) { s_lo = binLo; s_hi = binHi; s_need = need2; }
            __syncthreads();
        }
    }
    if (tid == 0) {
        if (!s_done) s_total += (float)s_need * expf(s_lo);   // degenerate: all equal
        g_Eh[n] = s_total;
    }
}

// --------- neg_rand: 512 smallest rand keys (stable ties), sum exp(pairs) ---
__global__ __launch_bounds__(512) void negrand_kernel(const int* __restrict__ label,
                                                      const float* __restrict__ flag,
                                                      const float* __restrict__ rnd) {
    __shared__ int   hist[NB];
    __shared__ unsigned long long list[CAP];
    __shared__ int   s_cnt, s_B, s_cntBelow, s_need, s_done;
    __shared__ float s_lo, s_hi, s_total;
    __shared__ float warpBuf[16];

    const int n = blockIdx.x;
    const int lbl = label[n];
    const float* row  = g_pairs + (size_t)n * BR;
    const float* rrow = rnd + (size_t)n * BR;
    const int tid = threadIdx.x, nt = blockDim.x;

    if (tid == 0) { s_total = 0.f; s_lo = -0.01f; s_hi = 1.01f; s_need = NEGN; s_done = 0; }
    __syncthreads();

    for (int iter = 0; iter < 6; ++iter) {
        if (s_done) break;
        const float lo = s_lo, hi = s_hi;
        const float scale = (float)NB / (hi - lo);
        for (int b = tid; b < NB; b += nt) hist[b] = 0;
        if (tid == 0) s_cnt = 0;
        __syncthreads();
        for (int j = tid; j < BR; j += nt) {
            if ((j % CLS) != lbl && (flag[j] > 0.f || g_colmap[j] >= 0)) {
                float k = rrow[j];
                if (k >= lo && k < hi) {
                    int b = (int)((k - lo) * scale);
                    b = b < 0 ? 0 : (b >= NB ? NB - 1 : b);
                    atomicAdd(&hist[b], 1);
                }
            }
        }
        __syncthreads();
        if (tid == 0) {
            int need = s_need, acc = 0, B = NB - 1;
            for (int b = 0; b < NB; b++) {
                if (acc + hist[b] >= need) { B = b; break; }
                acc += hist[b];
            }
            s_B = B; s_cntBelow = acc;
        }
        __syncthreads();
        const int B = s_B;
        const float binLo = lo + (float)B * (hi - lo) / NB;
        const float binHi = lo + (float)(B + 1) * (hi - lo) / NB;

        float myExp = 0.f;
        for (int j = tid; j < BR; j += nt) {
            if ((j % CLS) != lbl && (flag[j] > 0.f || g_colmap[j] >= 0)) {
                float k = rrow[j];
                if (k >= lo && k < hi) {
                    int b = (int)((k - lo) * scale);
                    b = b < 0 ? 0 : (b >= NB ? NB - 1 : b);
                    if (b < B) myExp += expf(row[j]);
                    else if (b == B) {
                        int p = atomicAdd(&s_cnt, 1);
                        if (p < CAP)
                            list[p] = ((unsigned long long)__float_as_uint(k) << 32) | (unsigned)j;
                    }
                }
            }
        }
        __syncthreads();
        float red = blockReduceSum(myExp, warpBuf);
        if (tid == 0) s_total += red;
        __syncthreads();

        const int cnt = s_cnt;
        const int need2 = s_need - s_cntBelow;
        if (cnt <= need2) {
            float e = 0.f;
            int lim = cnt < CAP ? cnt : CAP;
            for (int p = tid; p < lim; p += nt)
                e += expf(row[(unsigned)(list[p] & 0xffffffffull)]);
            float r2 = blockReduceSum(e, warpBuf);
            if (tid == 0) { s_total += r2; s_done = 1; }
            __syncthreads();
        } else if (cnt <= CAP) {
            int L = 2; while (L < cnt) L <<= 1;
            for (int p = tid; p < L; p += nt) if (p >= cnt) list[p] = 0xffffffffffffffffull;
            __syncthreads();
            for (int k = 2; k <= L; k <<= 1)
                for (int j2 = k >> 1; j2 > 0; j2 >>= 1) {
                    for (int i = tid; i < L; i += nt) {
                        int ixj = i ^ j2;
                        if (ixj > i) {
                            bool up = ((i & k) == 0);
                            unsigned long long a = list[i], b = list[ixj];
                            if (up ? (a > b) : (a < b)) { list[i] = b; list[ixj] = a; }
                        }
                    }
                    __syncthreads();
                }
            float e = 0.f;
            for (int p = tid; p < need2; p += nt)
                e += expf(row[(unsigned)(list[p] & 0xffffffffull)]);
            float r2 = blockReduceSum(e, warpBuf);
            if (tid == 0) { s_total += r2; s_done = 1; }
            __syncthreads();
        } else {
            if (tid == 0) { s_lo = binLo; s_hi = binHi; s_need = need2; }
            __syncthreads();
        }
    }
    if (tid == 0) {
        if (!s_done) s_total += (float)s_need * expf(s_lo);
        g_Er[n] = s_total;
    }
}

// ------------------------- loss reduce --------------------------------------
__global__ void loss_kernel() {
    int n = blockIdx.x, p = threadIdx.x;     // 512 blocks x 128 threads
    float pv = g_pos[n * POSN + p];
    float Eh = g_Eh[n], Er = g_Er[n];
    float e = expf(pv);
    double term = (log((double)(e + Eh)) - (double)pv) +
                  (log((double)(e + Er)) - (double)pv);
    __shared__ double red[128];
    red[p] = term;
    __syncthreads();
    for (int s = 64; s > 0; s >>= 1) {
        if (p < s) red[p] += red[p + s];
        __syncthreads();
    }
    if (p == 0) atomicAdd(&g_loss, red[0]);
}

__global__ void finalize_kernel(float* out) {
    out[0] = (float)(g_loss / (double)(BATCH * 2 * POSN));
}

// ------------------------- launcher -----------------------------------------
extern "C" void kernel_launch(void* const* d_in, const int* in_sizes, int n_in,
                              void* d_out, int out_size) {
    const float* f    = (const float*)d_in[0];   // (512, 256)
    const int*   lab  = (const int*)d_in[1];     // (512,)
    const int*   eidx = (const int*)d_in[2];     // (512,)
    const float* bank = (const float*)d_in[3];   // (41040, 256)
    const float* flag = (const float*)d_in[4];   // (41040,)
    const float* rnd  = (const float*)d_in[5];   // (512, 41040)
    float* out = (float*)d_out;

    init_loss_kernel<<<1, 1>>>();
    colmap_init_kernel<<<(BR + 255) / 256, 256>>>();
    colmap_scatter_kernel<<<2, 256>>>(eidx);
    gemm_kernel<<<dim3((BR + 63) / 64, BATCH / 64), 256>>>(f, bank);
    fixup_kernel<<<BATCH, 256>>>(f, eidx);
    pos_kernel<<<BATCH, 256>>>(lab, flag);
    neghard_kernel<<<BATCH, 512>>>(lab, flag);
    negrand_kernel<<<BATCH, 512>>>(lab, flag, rnd);
    loss_kernel<<<BATCH, 128>>>();
    finalize_kernel<<<1, 1>>>(out);
    (void)in_sizes; (void)n_in; (void)out_size;
}

// round 3
// speedup vs baseline: 1.6308x; 1.6308x over previous
#include <cuda_runtime.h>
#include <math.h>
#include <stdint.h>

#define BATCH 512
#define CH    256
#define CLS   60
#define MEMSZ 684
#define BR    41040
#define POSN  128
#define NEGN  512
#define NWORDS 1283          // ceil(BR/32)
#define CAPN  2048
#define NQ    (BR/4)         // 10260 float4 per row

// ------------------------- device scratch -----------------------------------
__device__ float    g_pairs[(size_t)BATCH * BR];   // 84 MB
__device__ float    g_pos[BATCH * POSN];
__device__ float    g_Eh[BATCH];
__device__ float    g_Er[BATCH];
__device__ uint32_t g_validbits[NWORDS];
__device__ uint32_t g_eqtab[CLS * 15];
__device__ double   g_loss;

// ------------------------- prep kernels -------------------------------------
__global__ void init_loss_kernel() { g_loss = 0.0; }

__global__ void prep_eqtab_kernel() {
    int e = blockIdx.x * blockDim.x + threadIdx.x;
    if (e < CLS * 15) {
        int lbl = e / 15, p = e % 15;
        int off = (32 * p) % 60;
        uint32_t m = 0;
        for (int b = 0; b < 32; b++) if ((off + b) % 60 == lbl) m |= 1u << b;
        g_eqtab[e] = m;
    }
}

__global__ void prep_valid_kernel(const float* __restrict__ flag) {
    int w = blockIdx.x * blockDim.x + threadIdx.x;
    if (w < NWORDS) {
        uint32_t m = 0; int base = w * 32;
        for (int b = 0; b < 32; b++) {
            int j = base + b;
            if (j < BR && flag[j] > 0.f) m |= 1u << b;
        }
        g_validbits[w] = m;
    }
}

__global__ void prep_scatter_kernel(const int* __restrict__ eidx) {
    int m = blockIdx.x * blockDim.x + threadIdx.x;
    if (m < BATCH) { int j = eidx[m]; atomicOr(&g_validbits[j >> 5], 1u << (j & 31)); }
}

// ------------------------- tf32 tensor-core GEMM ----------------------------
// P[512, 41040] = F[512,256] @ bank[41040,256]^T
// Block tile 128(M=batch) x 128(N=bank), BK=32, 128 threads = 4 warps (2x2),
// warp tile 64x64, mma.sync m16n8k8 tf32 (truncation; normalized inputs ->
// logit error ~1e-3 relative, fine for 1e-3 loss tolerance).
#define GBM 128
#define GBN 128
#define GBK 32
#define GPAD 36
#define GKITERS 8

__device__ __forceinline__ void mma_tf32(float* c, const uint32_t* a, const uint32_t* b) {
    asm volatile(
        "mma.sync.aligned.m16n8k8.row.col.f32.tf32.tf32.f32 "
        "{%0,%1,%2,%3},{%4,%5,%6,%7},{%8,%9},{%0,%1,%2,%3};"
        : "+f"(c[0]), "+f"(c[1]), "+f"(c[2]), "+f"(c[3])
        : "r"(a[0]), "r"(a[1]), "r"(a[2]), "r"(a[3]), "r"(b[0]), "r"(b[1]));
}

__global__ __launch_bounds__(128) void gemm_tf32_kernel(const float* __restrict__ F,
                                                        const float* __restrict__ BK_) {
    extern __shared__ float sm[];
    // As[2][128][36], Bs[2][128][36]
    float* As = sm;
    float* Bs = sm + 2 * GBM * GPAD;
#define ASM(bf, r, c) As[(bf) * GBM * GPAD + (r) * GPAD + (c)]
#define BSM(bf, r, c) Bs[(bf) * GBM * GPAD + (r) * GPAD + (c)]

    const int bj = blockIdx.x * GBN;
    const int bn = blockIdx.y * GBM;
    const int tid = threadIdx.x;
    const int wid = tid >> 5, lane = tid & 31;
    const int wm = (wid >> 1) * 64, wn = (wid & 1) * 64;
    const int tr = lane >> 2, tc = lane & 3;

    float acc[4][8][4];
#pragma unroll
    for (int i = 0; i < 4; i++)
#pragma unroll
        for (int j = 0; j < 8; j++)
#pragma unroll
            for (int k = 0; k < 4; k++) acc[i][j][k] = 0.f;

    auto load_stage = [&](int buf, int kt) {
        int k0 = kt * GBK;
#pragma unroll
        for (int i = 0; i < 8; i++) {
            int slot = tid + i * 128;          // 0..1023
            int r = slot >> 3;
            int kq = (slot & 7) * 4;
            uint32_t da = (uint32_t)__cvta_generic_to_shared(&ASM(buf, r, kq));
            const float* ga = F + (size_t)(bn + r) * CH + k0 + kq;
            asm volatile("cp.async.cg.shared.global [%0], [%1], 16;" :: "r"(da), "l"(ga));
            int j = bj + r;
            int ok = (j < BR) ? 16 : 0;
            const float* gb = BK_ + (size_t)(j < BR ? j : 0) * CH + k0 + kq;
            uint32_t db = (uint32_t)__cvta_generic_to_shared(&BSM(buf, r, kq));
            asm volatile("cp.async.cg.shared.global [%0], [%1], 16, %2;" :: "r"(db), "l"(gb), "r"(ok));
        }
    };

    load_stage(0, 0);
    asm volatile("cp.async.commit_group;");

    for (int kt = 0; kt < GKITERS; kt++) {
        asm volatile("cp.async.wait_group 0;");
        __syncthreads();
        if (kt + 1 < GKITERS) {
            load_stage((kt + 1) & 1, kt + 1);
            asm volatile("cp.async.commit_group;");
        }
        int b = kt & 1;
#pragma unroll
        for (int ks = 0; ks < 4; ks++) {
            int kk = ks * 8;
            uint32_t af[4][4], bf[8][2];
#pragma unroll
            for (int mi = 0; mi < 4; mi++) {
                int r0 = wm + mi * 16 + tr;
                af[mi][0] = __float_as_uint(ASM(b, r0,     kk + tc));
                af[mi][1] = __float_as_uint(ASM(b, r0 + 8, kk + tc));
                af[mi][2] = __float_as_uint(ASM(b, r0,     kk + tc + 4));
                af[mi][3] = __float_as_uint(ASM(b, r0 + 8, kk + tc + 4));
            }
#pragma unroll
            for (int ni = 0; ni < 8; ni++) {
                int r0 = wn + ni * 8 + tr;
                bf[ni][0] = __float_as_uint(BSM(b, r0, kk + tc));
                bf[ni][1] = __float_as_uint(BSM(b, r0, kk + tc + 4));
            }
#pragma unroll
            for (int mi = 0; mi < 4; mi++)
#pragma unroll
                for (int ni = 0; ni < 8; ni++) mma_tf32(acc[mi][ni], af[mi], bf[ni]);
        }
    }

#pragma unroll
    for (int mi = 0; mi < 4; mi++) {
        int m = bn + wm + mi * 16 + tr;
        float* p0 = &g_pairs[(size_t)m * BR];
        float* p1 = &g_pairs[(size_t)(m + 8) * BR];
#pragma unroll
        for (int ni = 0; ni < 8; ni++) {
            int col = bj + wn + ni * 8 + tc * 2;
            if (col < BR) {
                *(float2*)(p0 + col) = make_float2(acc[mi][ni][0], acc[mi][ni][1]);
                *(float2*)(p1 + col) = make_float2(acc[mi][ni][2], acc[mi][ni][3]);
            }
        }
    }
#undef ASM
#undef BSM
}

// ------------------------- fixup: enqueued columns = F @ f_m (fp32 exact) ---
__global__ void fixup_kernel(const float* __restrict__ F, const int* __restrict__ eidx) {
    int m = blockIdx.x;
    __shared__ float fm[CH];
    for (int k = threadIdx.x; k < CH; k += blockDim.x) fm[k] = F[(size_t)m * CH + k];
    __syncthreads();
    int col = eidx[m];
    for (int n = threadIdx.x; n < BATCH; n += blockDim.x) {
        const float* fn = &F[(size_t)n * CH];
        float s = 0.f;
#pragma unroll 8
        for (int k = 0; k < CH; k++) s += fn[k] * fm[k];
        g_pairs[(size_t)n * BR + col] = s;
    }
}

// ------------------------- positives: 128 smallest of 684 -------------------
__global__ __launch_bounds__(256) void pos_kernel(const int* __restrict__ label) {
    int n = blockIdx.x;
    __shared__ float v[1024];
    int lbl = label[n];
    const float* row = g_pairs + (size_t)n * BR;
    for (int t = threadIdx.x; t < 1024; t += 256) {
        float x = INFINITY;
        if (t < MEMSZ) {
            int col = lbl + CLS * t;
            if ((g_validbits[col >> 5] >> (col & 31)) & 1) x = row[col];
        }
        v[t] = x;
    }
    __syncthreads();
    for (int k = 2; k <= 1024; k <<= 1)
        for (int j2 = k >> 1; j2 > 0; j2 >>= 1) {
            for (int i = threadIdx.x; i < 1024; i += 256) {
                int ixj = i ^ j2;
                if (ixj > i) {
                    bool up = ((i & k) == 0);
                    float a = v[i], b = v[ixj];
                    if (up ? (a > b) : (a < b)) { v[i] = b; v[ixj] = a; }
                }
            }
            __syncthreads();
        }
    for (int t = threadIdx.x; t < POSN; t += 256) g_pos[n * POSN + t] = v[t];
}

// ------------------------- helpers ------------------------------------------
__device__ __forceinline__ uint32_t fkey(float v) {           // order-preserving
    uint32_t u = __float_as_uint(v);
    return (u & 0x80000000u) ? ~u : (u | 0x80000000u);
}
__device__ __forceinline__ float unfkey(uint32_t u) {
    uint32_t b = (u & 0x80000000u) ? (u & 0x7FFFFFFFu) : ~u;
    return __uint_as_float(b);
}

__device__ __forceinline__ int blockReduceInt(int c, int* s_red) {
    __syncthreads();
    if (threadIdx.x == 0) *s_red = 0;
    __syncthreads();
#pragma unroll
    for (int o = 16; o > 0; o >>= 1) c += __shfl_down_sync(0xffffffffu, c, o);
    if ((threadIdx.x & 31) == 0) atomicAdd(s_red, c);
    __syncthreads();
    return *s_red;
}
__device__ __forceinline__ float blockReduceFloat(float v, float* warpBuf) {
#pragma unroll
    for (int o = 16; o > 0; o >>= 1) v += __shfl_down_sync(0xffffffffu, v, o);
    int lane = threadIdx.x & 31, w = threadIdx.x >> 5;
    if (lane == 0) warpBuf[w] = v;
    __syncthreads();
    float s = 0.f;
    if (threadIdx.x == 0) {
        int nw = blockDim.x >> 5;
        for (int i = 0; i < nw; i++) s += warpBuf[i];
    }
    __syncthreads();
    return s;   // thread 0 only
}

// -------- fused negative selection (hard top-512 values + rand 512 keys) ----
__global__ __launch_bounds__(512) void negsel_kernel(const int* __restrict__ label,
                                                     const float* __restrict__ rnd) {
    __shared__ uint32_t s_mask[NWORDS];
    __shared__ uint32_t s_listH[CAPN];
    __shared__ unsigned long long s_listR[CAPN];
    __shared__ float    s_samp[1024];
    __shared__ int      s_cntH, s_cntR, s_red;
    __shared__ float    s_warp[16];
    __shared__ float    s_res;

    const int n = blockIdx.x;
    const int lbl = label[n];
    const float* row  = g_pairs + (size_t)n * BR;
    const float* rrow = rnd + (size_t)n * BR;
    const int tid = threadIdx.x;

    // negative-validity bitmask for this row
    for (int w = tid; w < NWORDS; w += 512)
        s_mask[w] = g_validbits[w] & ~g_eqtab[lbl * 15 + (w % 15)];
    if (tid == 0) { s_cntH = 0; s_cntR = 0; }
    __syncthreads();

    // ---- sampled thresholds (1024 deterministic samples, 32nd order stat) --
    for (int s = tid; s < 1024; s += 512) {
        int j = 37 * s + 11;
        bool ok = (s_mask[j >> 5] >> (j & 31)) & 1;
        s_samp[s] = ok ? row[j] : -INFINITY;
    }
    __syncthreads();
    for (int k = 2; k <= 1024; k <<= 1)
        for (int j2 = k >> 1; j2 > 0; j2 >>= 1) {
            for (int i = tid; i < 1024; i += 512) {
                int ixj = i ^ j2;
                if (ixj > i) {
                    bool up = ((i & k) == 0);
                    float a = s_samp[i], b = s_samp[ixj];
                    if (up ? (a > b) : (a < b)) { s_samp[i] = b; s_samp[ixj] = a; }
                }
            }
            __syncthreads();
        }
    const float Tv = s_samp[1024 - 32];
    __syncthreads();
    for (int s = tid; s < 1024; s += 512) {
        int j = 37 * s + 11;
        bool ok = (s_mask[j >> 5] >> (j & 31)) & 1;
        s_samp[s] = ok ? rrow[j] : INFINITY;
    }
    __syncthreads();
    for (int k = 2; k <= 1024; k <<= 1)
        for (int j2 = k >> 1; j2 > 0; j2 >>= 1) {
            for (int i = tid; i < 1024; i += 512) {
                int ixj = i ^ j2;
                if (ixj > i) {
                    bool up = ((i & k) == 0);
                    float a = s_samp[i], b = s_samp[ixj];
                    if (up ? (a > b) : (a < b)) { s_samp[i] = b; s_samp[ixj] = a; }
                }
            }
            __syncthreads();
        }
    const float Tr = s_samp[31];
    __syncthreads();

    // ---- single fused scan: collect candidates past thresholds -------------
    for (int q = tid; q < NQ; q += 512) {
        uint32_t mb = (s_mask[q >> 3] >> ((q & 7) << 2)) & 0xF;
        if (!mb) continue;
        float4 v = ((const float4*)row)[q];
        float4 r = ((const float4*)rrow)[q];
        int j0 = q << 2;
        float vv[4] = {v.x, v.y, v.z, v.w};
        float rr[4] = {r.x, r.y, r.z, r.w};
#pragma unroll
        for (int e = 0; e < 4; e++) {
            if ((mb >> e) & 1) {
                if (vv[e] >= Tv) {
                    int p = atomicAdd(&s_cntH, 1);
                    if (p < CAPN) s_listH[p] = fkey(vv[e]);
                }
                if (rr[e] <= Tr) {
                    int p = atomicAdd(&s_cntR, 1);
                    if (p < CAPN)
                        s_listR[p] = ((unsigned long long)__float_as_uint(rr[e]) << 32) |
                                     (unsigned)(j0 + e);
                }
            }
        }
    }
    __syncthreads();
    const int cntH = s_cntH, cntR = s_cntR;

    // ============ HARD: exact sum of exp of top-512 values ==================
    {
        uint32_t lo = 0, hi = 0xFFFFFFFFu;
        bool primary = (cntH >= NEGN && cntH <= CAPN);
        while (lo < hi) {
            uint32_t d = hi - lo;
            uint32_t mid = lo + (d >> 1) + (d & 1);
            int c = 0;
            if (primary) {
                for (int i = tid; i < cntH; i += 512) c += (s_listH[i] >= mid);
            } else {
                for (int j = tid; j < BR; j += 512)
                    if ((s_mask[j >> 5] >> (j & 31)) & 1) c += (fkey(row[j]) >= mid);
            }
            c = blockReduceInt(c, &s_red);
            if (c >= NEGN) lo = mid; else hi = mid - 1;
        }
        // count strictly greater + sum of their exps
        int cg = 0; float se = 0.f;
        if (primary) {
            for (int i = tid; i < cntH; i += 512) {
                uint32_t u = s_listH[i];
                if (u > lo) { cg++; se += expf(unfkey(u)); }
            }
        } else {
            for (int j = tid; j < BR; j += 512)
                if ((s_mask[j >> 5] >> (j & 31)) & 1) {
                    float x = row[j];
                    if (fkey(x) > lo) { cg++; se += expf(x); }
                }
        }
        cg = blockReduceInt(cg, &s_red);
        float tot = blockReduceFloat(se, s_warp);
        if (tid == 0) g_Eh[n] = tot + (float)(NEGN - cg) * expf(unfkey(lo));
        __syncthreads();
    }

    // ============ RAND: exact 512 smallest (key,idx), sum exp(pairs) ========
    {
        unsigned long long lo = 0ull, hi = 0xFFFFFFFFFFFFFFFFull;
        bool primary = (cntR >= NEGN && cntR <= CAPN);
        while (lo < hi) {
            unsigned long long mid = lo + ((hi - lo) >> 1);
            int c = 0;
            if (primary) {
                for (int i = tid; i < cntR; i += 512) c += (s_listR[i] <= mid);
            } else {
                for (int j = tid; j < BR; j += 512)
                    if ((s_mask[j >> 5] >> (j & 31)) & 1) {
                        unsigned long long w =
                            ((unsigned long long)__float_as_uint(rrow[j]) << 32) | (unsigned)j;
                        c += (w <= mid);
                    }
            }
            c = blockReduceInt(c, &s_red);
            if (c >= NEGN) hi = mid; else lo = mid + 1;
        }
        float se = 0.f;
        if (primary) {
            for (int i = tid; i < cntR; i += 512) {
                unsigned long long w = s_listR[i];
                if (w <= lo) se += expf(row[(unsigned)(w & 0xFFFFFFFFull)]);
            }
        } else {
            for (int j = tid; j < BR; j += 512)
                if ((s_mask[j >> 5] >> (j & 31)) & 1) {
                    unsigned long long w =
                        ((unsigned long long)__float_as_uint(rrow[j]) << 32) | (unsigned)j;
                    if (w <= lo) se += expf(row[j]);
                }
        }
        float tot = blockReduceFloat(se, s_warp);
        if (tid == 0) g_Er[n] = tot;
        (void)s_res;
    }
}

// ------------------------- loss reduce --------------------------------------
__global__ void loss_kernel() {
    int n = blockIdx.x, p = threadIdx.x;
    float pv = g_pos[n * POSN + p];
    float Eh = g_Eh[n], Er = g_Er[n];
    float e = expf(pv);
    double term = (log((double)(e + Eh)) - (double)pv) +
                  (log((double)(e + Er)) - (double)pv);
    __shared__ double red[128];
    red[p] = term;
    __syncthreads();
    for (int s = 64; s > 0; s >>= 1) {
        if (p < s) red[p] += red[p + s];
        __syncthreads();
    }
    if (p == 0) atomicAdd(&g_loss, red[0]);
}

__global__ void finalize_kernel(float* out) {
    out[0] = (float)(g_loss / (double)(BATCH * 2 * POSN));
}

// ------------------------- launcher -----------------------------------------
extern "C" void kernel_launch(void* const* d_in, const int* in_sizes, int n_in,
                              void* d_out, int out_size) {
    const float* f    = (const float*)d_in[0];
    const int*   lab  = (const int*)d_in[1];
    const int*   eidx = (const int*)d_in[2];
    const float* bank = (const float*)d_in[3];
    const float* flag = (const float*)d_in[4];
    const float* rnd  = (const float*)d_in[5];
    float* out = (float*)d_out;

    const int GEMM_SMEM = 2 * 2 * GBM * GPAD * 4;   // 73728 bytes
    cudaFuncSetAttribute(gemm_tf32_kernel,
                         cudaFuncAttributeMaxDynamicSharedMemorySize, GEMM_SMEM);

    init_loss_kernel<<<1, 1>>>();
    prep_eqtab_kernel<<<4, 256>>>();
    prep_valid_kernel<<<(NWORDS + 255) / 256, 256>>>(flag);
    prep_scatter_kernel<<<2, 256>>>(eidx);
    gemm_tf32_kernel<<<dim3((BR + GBN - 1) / GBN, BATCH / GBM), 128, GEMM_SMEM>>>(f, bank);
    fixup_kernel<<<BATCH, 256>>>(f, eidx);
    pos_kernel<<<BATCH, 256>>>(lab);
    negsel_kernel<<<BATCH, 512>>>(lab, rnd);
    loss_kernel<<<BATCH, 128>>>();
    finalize_kernel<<<1, 1>>>(out);
    (void)in_sizes; (void)n_in; (void)out_size;
}

// round 4
// speedup vs baseline: 1.9591x; 1.2013x over previous
#include <cuda_runtime.h>
#include <math.h>
#include <stdint.h>

#define BATCH 512
#define CH    256
#define CLS   60
#define MEMSZ 684
#define BR    41040
#define POSN  128
#define NEGN  512
#define NWORDS 1283          // ceil(BR/32)
#define CAPN  2048
#define NQ    (BR/4)         // 10260 float4 per row

typedef unsigned long long u64;

// ------------------------- device scratch -----------------------------------
__device__ float    g_pairs[(size_t)BATCH * BR];   // 84 MB
__device__ uint32_t g_validbits[NWORDS];
__device__ uint32_t g_eqtab[CLS * 15];
__device__ double   g_loss;

// ------------------------- prep ---------------------------------------------
__global__ void prep_kernel(const float* __restrict__ flag) {
    int i = blockIdx.x * blockDim.x + threadIdx.x;
    if (i == 0) g_loss = 0.0;
    if (i < CLS * 15) {
        int lbl = i / 15, p = i % 15;
        int off = (32 * p) % 60;
        uint32_t m = 0;
        for (int b = 0; b < 32; b++) if ((off + b) % 60 == lbl) m |= 1u << b;
        g_eqtab[i] = m;
    }
    if (i < NWORDS) {
        uint32_t m = 0; int base = i * 32;
        for (int b = 0; b < 32; b++) {
            int j = base + b;
            if (j < BR && flag[j] > 0.f) m |= 1u << b;
        }
        g_validbits[i] = m;
    }
}

__global__ void scatter_kernel(const int* __restrict__ eidx) {
    int m = blockIdx.x * blockDim.x + threadIdx.x;
    if (m < BATCH) { int j = eidx[m]; atomicOr(&g_validbits[j >> 5], 1u << (j & 31)); }
}

// ------------------------- tf32 tensor-core GEMM (unchanged) ----------------
#define GBM 128
#define GBN 128
#define GBK 32
#define GPAD 36
#define GKITERS 8

__device__ __forceinline__ void mma_tf32(float* c, const uint32_t* a, const uint32_t* b) {
    asm volatile(
        "mma.sync.aligned.m16n8k8.row.col.f32.tf32.tf32.f32 "
        "{%0,%1,%2,%3},{%4,%5,%6,%7},{%8,%9},{%0,%1,%2,%3};"
        : "+f"(c[0]), "+f"(c[1]), "+f"(c[2]), "+f"(c[3])
        : "r"(a[0]), "r"(a[1]), "r"(a[2]), "r"(a[3]), "r"(b[0]), "r"(b[1]));
}

__global__ __launch_bounds__(128) void gemm_tf32_kernel(const float* __restrict__ F,
                                                        const float* __restrict__ BK_) {
    extern __shared__ float sm[];
    float* As = sm;
    float* Bs = sm + 2 * GBM * GPAD;
#define ASM(bf, r, c) As[(bf) * GBM * GPAD + (r) * GPAD + (c)]
#define BSM(bf, r, c) Bs[(bf) * GBM * GPAD + (r) * GPAD + (c)]

    const int bj = blockIdx.x * GBN;
    const int bn = blockIdx.y * GBM;
    const int tid = threadIdx.x;
    const int wid = tid >> 5, lane = tid & 31;
    const int wm = (wid >> 1) * 64, wn = (wid & 1) * 64;
    const int tr = lane >> 2, tc = lane & 3;

    float acc[4][8][4];
#pragma unroll
    for (int i = 0; i < 4; i++)
#pragma unroll
        for (int j = 0; j < 8; j++)
#pragma unroll
            for (int k = 0; k < 4; k++) acc[i][j][k] = 0.f;

    auto load_stage = [&](int buf, int kt) {
        int k0 = kt * GBK;
#pragma unroll
        for (int i = 0; i < 8; i++) {
            int slot = tid + i * 128;
            int r = slot >> 3;
            int kq = (slot & 7) * 4;
            uint32_t da = (uint32_t)__cvta_generic_to_shared(&ASM(buf, r, kq));
            const float* ga = F + (size_t)(bn + r) * CH + k0 + kq;
            asm volatile("cp.async.cg.shared.global [%0], [%1], 16;" :: "r"(da), "l"(ga));
            int j = bj + r;
            int ok = (j < BR) ? 16 : 0;
            const float* gb = BK_ + (size_t)(j < BR ? j : 0) * CH + k0 + kq;
            uint32_t db = (uint32_t)__cvta_generic_to_shared(&BSM(buf, r, kq));
            asm volatile("cp.async.cg.shared.global [%0], [%1], 16, %2;" :: "r"(db), "l"(gb), "r"(ok));
        }
    };

    load_stage(0, 0);
    asm volatile("cp.async.commit_group;");

    for (int kt = 0; kt < GKITERS; kt++) {
        asm volatile("cp.async.wait_group 0;");
        __syncthreads();
        if (kt + 1 < GKITERS) {
            load_stage((kt + 1) & 1, kt + 1);
            asm volatile("cp.async.commit_group;");
        }
        int b = kt & 1;
#pragma unroll
        for (int ks = 0; ks < 4; ks++) {
            int kk = ks * 8;
            uint32_t af[4][4], bf[8][2];
#pragma unroll
            for (int mi = 0; mi < 4; mi++) {
                int r0 = wm + mi * 16 + tr;
                af[mi][0] = __float_as_uint(ASM(b, r0,     kk + tc));
                af[mi][1] = __float_as_uint(ASM(b, r0 + 8, kk + tc));
                af[mi][2] = __float_as_uint(ASM(b, r0,     kk + tc + 4));
                af[mi][3] = __float_as_uint(ASM(b, r0 + 8, kk + tc + 4));
            }
#pragma unroll
            for (int ni = 0; ni < 8; ni++) {
                int r0 = wn + ni * 8 + tr;
                bf[ni][0] = __float_as_uint(BSM(b, r0, kk + tc));
                bf[ni][1] = __float_as_uint(BSM(b, r0, kk + tc + 4));
            }
#pragma unroll
            for (int mi = 0; mi < 4; mi++)
#pragma unroll
                for (int ni = 0; ni < 8; ni++) mma_tf32(acc[mi][ni], af[mi], bf[ni]);
        }
    }

#pragma unroll
    for (int mi = 0; mi < 4; mi++) {
        int m = bn + wm + mi * 16 + tr;
        float* p0 = &g_pairs[(size_t)m * BR];
        float* p1 = &g_pairs[(size_t)(m + 8) * BR];
#pragma unroll
        for (int ni = 0; ni < 8; ni++) {
            int col = bj + wn + ni * 8 + tc * 2;
            if (col < BR) {
                *(float2*)(p0 + col) = make_float2(acc[mi][ni][0], acc[mi][ni][1]);
                *(float2*)(p1 + col) = make_float2(acc[mi][ni][2], acc[mi][ni][3]);
            }
        }
    }
#undef ASM
#undef BSM
}

// ------------------------- fixup (fp32 exact) -------------------------------
__global__ void fixup_kernel(const float* __restrict__ F, const int* __restrict__ eidx) {
    int m = blockIdx.x;
    __shared__ float fm[CH];
    for (int k = threadIdx.x; k < CH; k += blockDim.x) fm[k] = F[(size_t)m * CH + k];
    __syncthreads();
    int col = eidx[m];
    for (int n = threadIdx.x; n < BATCH; n += blockDim.x) {
        const float* fn = &F[(size_t)n * CH];
        float s = 0.f;
#pragma unroll 8
        for (int k = 0; k < CH; k++) s += fn[k] * fm[k];
        g_pairs[(size_t)n * BR + col] = s;
    }
}

// ------------------------- helpers ------------------------------------------
__device__ __forceinline__ uint32_t fkey(float v) {
    uint32_t u = __float_as_uint(v);
    return (u & 0x80000000u) ? ~u : (u | 0x80000000u);
}
__device__ __forceinline__ float unfkey(uint32_t u) {
    uint32_t b = (u & 0x80000000u) ? (u & 0x7FFFFFFFu) : ~u;
    return __uint_as_float(b);
}

__device__ __forceinline__ int warpRedInt(int c) {
#pragma unroll
    for (int o = 16; o > 0; o >>= 1) c += __shfl_xor_sync(0xffffffffu, c, o);
    return c;
}
__device__ __forceinline__ float warpRedF(float v) {
#pragma unroll
    for (int o = 16; o > 0; o >>= 1) v += __shfl_xor_sync(0xffffffffu, v, o);
    return v;
}

// warp-private rank selection (shfl-only, no block syncs)
__device__ uint32_t warp_sel_largest_u32(const uint32_t* a, int len, int need) {
    int lane = threadIdx.x & 31;
    uint32_t lo = 0, hi = 0xFFFFFFFFu;
    while (lo < hi) {
        uint32_t d = hi - lo;
        uint32_t mid = lo + (d >> 1) + (d & 1);
        int c = 0;
        for (int i = lane; i < len; i += 32) c += (a[i] >= mid);
        c = warpRedInt(c);
        if (c >= need) lo = mid; else hi = mid - 1;
    }
    return lo;
}
__device__ uint32_t warp_sel_smallest_u32(const uint32_t* a, int len, int need) {
    int lane = threadIdx.x & 31;
    uint32_t lo = 0, hi = 0xFFFFFFFFu;
    while (lo < hi) {
        uint32_t mid = lo + ((hi - lo) >> 1);
        int c = 0;
        for (int i = lane; i < len; i += 32) c += (a[i] <= mid);
        c = warpRedInt(c);
        if (c >= need) hi = mid; else lo = mid + 1;
    }
    return lo;
}
__device__ u64 warp_sel_smallest_u64(const u64* a, int len, int need) {
    int lane = threadIdx.x & 31;
    u64 lo = 0ull, hi = 0xFFFFFFFFFFFFFFFFull;
    while (lo < hi) {
        u64 mid = lo + ((hi - lo) >> 1);
        int c = 0;
        for (int i = lane; i < len; i += 32) c += (a[i] <= mid);
        c = warpRedInt(c);
        if (c >= need) hi = mid; else lo = mid + 1;
    }
    return lo;
}
__device__ uint32_t warp_sel_smallest_fkey(const float* a, int len, int need) {
    int lane = threadIdx.x & 31;
    uint32_t lo = 0, hi = 0xFFFFFFFFu;
    while (lo < hi) {
        uint32_t mid = lo + ((hi - lo) >> 1);
        int c = 0;
        for (int i = lane; i < len; i += 32) c += (fkey(a[i]) <= mid);
        c = warpRedInt(c);
        if (c >= need) hi = mid; else lo = mid + 1;
    }
    return lo;
}

__device__ __forceinline__ int blockReduceInt(int c, int* s_red) {
    __syncthreads();
    if (threadIdx.x == 0) *s_red = 0;
    __syncthreads();
    c = warpRedInt(c);
    if ((threadIdx.x & 31) == 0) atomicAdd(s_red, c);
    __syncthreads();
    return *s_red;
}
__device__ __forceinline__ float blockReduceFloat(float v, float* warpBuf) {
    v = warpRedF(v);
    int lane = threadIdx.x & 31, w = threadIdx.x >> 5;
    if (lane == 0) warpBuf[w] = v;
    __syncthreads();
    float s = 0.f;
    if (threadIdx.x == 0)
        for (int i = 0; i < (int)(blockDim.x >> 5); i++) s += warpBuf[i];
    __syncthreads();
    return s;   // thread 0 only
}
__device__ __forceinline__ double blockReduceDouble(double v, double* warpBuf) {
#pragma unroll
    for (int o = 16; o > 0; o >>= 1) v += __shfl_xor_sync(0xffffffffu, v, o);
    int lane = threadIdx.x & 31, w = threadIdx.x >> 5;
    if (lane == 0) warpBuf[w] = v;
    __syncthreads();
    double s = 0.0;
    if (threadIdx.x == 0)
        for (int i = 0; i < (int)(blockDim.x >> 5); i++) s += warpBuf[i];
    __syncthreads();
    return s;   // thread 0 only
}

__device__ __forceinline__ double lterm(float pv, float Eh, float Er) {
    float e = expf(pv);
    return (double)(logf(e + Eh) - pv) + (double)(logf(e + Er) - pv);
}

// ------- fused: hard top-512 + rand 512 + pos-128 + per-row loss ------------
__global__ __launch_bounds__(512) void negsel_kernel(const int* __restrict__ label,
                                                     const float* __restrict__ rnd) {
    __shared__ uint32_t s_negmask[NWORDS];
    __shared__ uint32_t s_posmask[NWORDS];
    __shared__ uint32_t s_listH[CAPN];
    __shared__ u64      s_listR[CAPN];
    __shared__ uint32_t s_sampH[1024];
    __shared__ uint32_t s_sampR[1024];
    __shared__ float    s_pos[MEMSZ];
    __shared__ int      s_cntH, s_cntR, s_red;
    __shared__ float    s_warp[16];
    __shared__ double   s_warpd[16];
    __shared__ uint32_t s_thrH, s_thrP, s_thrRs;
    __shared__ u64      s_thrR;
    __shared__ float    s_Eh, s_Er;

    const int n = blockIdx.x;
    const int lbl = label[n];
    const float* row  = g_pairs + (size_t)n * BR;
    const float* rrow = rnd + (size_t)n * BR;
    const int tid = threadIdx.x, wid = tid >> 5, lane = tid & 31;

    for (int w = tid; w < NWORDS; w += 512) {
        uint32_t v = g_validbits[w], e = g_eqtab[lbl * 15 + (w % 15)];
        s_negmask[w] = v & ~e;
        s_posmask[w] = v & e;
    }
    for (int i = tid; i < MEMSZ; i += 512) s_pos[i] = INFINITY;
    if (tid == 0) { s_cntH = 0; s_cntR = 0; }
    __syncthreads();

    // ---- 1024 deterministic samples each for hard & rand -------------------
    for (int s = tid; s < 1024; s += 512) {
        int j = 37 * s + 11;
        bool ok = (s_negmask[j >> 5] >> (j & 31)) & 1;
        s_sampH[s] = ok ? fkey(row[j]) : 0u;                     // -inf key
        s_sampR[s] = ok ? __float_as_uint(rrow[j]) : 0xFFFFFFFFu; // huge key
    }
    __syncthreads();
    if (wid == 0) { uint32_t t = warp_sel_largest_u32(s_sampH, 1024, 32);
                    if (lane == 0) s_thrH = t; }
    if (wid == 1) { uint32_t t = warp_sel_smallest_u32(s_sampR, 1024, 32);
                    if (lane == 0) s_thrRs = t; }
    __syncthreads();
    const float thrHs = unfkey(s_thrH);                   // attained sample value
    const float thrRs = __uint_as_float(s_thrRs);         // attained sample value

    // ---- single fused scan --------------------------------------------------
    for (int q = tid; q < NQ; q += 512) {
        uint32_t nm = (s_negmask[q >> 3] >> ((q & 7) << 2)) & 0xF;
        uint32_t pm = (s_posmask[q >> 3] >> ((q & 7) << 2)) & 0xF;
        if (!(nm | pm)) continue;
        float4 v = ((const float4*)row)[q];
        float vv[4] = {v.x, v.y, v.z, v.w};
        int j0 = q << 2;
        if (pm) {
#pragma unroll
            for (int e = 0; e < 4; e++)
                if ((pm >> e) & 1)
                    s_pos[(unsigned)(j0 + e - lbl) / 60u] = vv[e];
        }
        if (nm) {
            float4 r = ((const float4*)rrow)[q];
            float rr[4] = {r.x, r.y, r.z, r.w};
#pragma unroll
            for (int e = 0; e < 4; e++) {
                if ((nm >> e) & 1) {
                    if (vv[e] >= thrHs) {
                        int p = atomicAdd(&s_cntH, 1);
                        if (p < CAPN) s_listH[p] = fkey(vv[e]);
                    }
                    if (rr[e] <= thrRs) {
                        int p = atomicAdd(&s_cntR, 1);
                        if (p < CAPN)
                            s_listR[p] = ((u64)__float_as_uint(rr[e]) << 32) |
                                         (unsigned)(j0 + e);
                    }
                }
            }
        }
    }
    __syncthreads();
    const int cntH = s_cntH, cntR = s_cntR;
    const bool okH = (cntH >= NEGN && cntH <= CAPN);
    const bool okR = (cntR >= NEGN && cntR <= CAPN);

    // ---- thresholds: warps 0/1/2 in parallel (shfl-only) --------------------
    if (okH && wid == 0) { uint32_t t = warp_sel_largest_u32(s_listH, cntH, NEGN);
                           if (lane == 0) s_thrH = t; }
    if (okR && wid == 1) { u64 t = warp_sel_smallest_u64(s_listR, cntR, NEGN);
                           if (lane == 0) s_thrR = t; }
    if (wid == 2) { uint32_t t = warp_sel_smallest_fkey(s_pos, MEMSZ, POSN);
                    if (lane == 0) s_thrP = t; }
    __syncthreads();

    // ---- rare fallbacks: block-wide bisect over gmem (uniform branches) -----
    if (!okH) {
        uint32_t lo = 0, hi = 0xFFFFFFFFu;
        while (lo < hi) {
            uint32_t d = hi - lo;
            uint32_t mid = lo + (d >> 1) + (d & 1);
            int c = 0;
            for (int j = tid; j < BR; j += 512)
                if ((s_negmask[j >> 5] >> (j & 31)) & 1) c += (fkey(row[j]) >= mid);
            c = blockReduceInt(c, &s_red);
            if (c >= NEGN) lo = mid; else hi = mid - 1;
        }
        if (tid == 0) s_thrH = lo;
        __syncthreads();
    }
    if (!okR) {
        u64 lo = 0ull, hi = 0xFFFFFFFFFFFFFFFFull;
        while (lo < hi) {
            u64 mid = lo + ((hi - lo) >> 1);
            int c = 0;
            for (int j = tid; j < BR; j += 512)
                if ((s_negmask[j >> 5] >> (j & 31)) & 1) {
                    u64 w = ((u64)__float_as_uint(rrow[j]) << 32) | (unsigned)j;
                    c += (w <= mid);
                }
            c = blockReduceInt(c, &s_red);
            if (c >= NEGN) hi = mid; else lo = mid + 1;
        }
        if (tid == 0) s_thrR = lo;
        __syncthreads();
    }

    // ---- Eh / Er sums -------------------------------------------------------
    if (okH && wid == 0) {
        uint32_t t = s_thrH;
        int cg = 0; float se = 0.f;
        for (int i = lane; i < cntH; i += 32) {
            uint32_t u = s_listH[i];
            if (u > t) { cg++; se += expf(unfkey(u)); }
        }
        cg = warpRedInt(cg); se = warpRedF(se);
        if (lane == 0) s_Eh = se + (float)(NEGN - cg) * expf(unfkey(t));
    }
    if (okR && wid == 1) {
        u64 t = s_thrR;
        float se = 0.f;
        for (int i = lane; i < cntR; i += 32) {
            u64 w = s_listR[i];
            if (w <= t) se += expf(row[(unsigned)(w & 0xFFFFFFFFull)]);
        }
        se = warpRedF(se);
        if (lane == 0) s_Er = se;
    }
    __syncthreads();
    if (!okH) {
        uint32_t t = s_thrH;
        int cg = 0; float se = 0.f;
        for (int j = tid; j < BR; j += 512)
            if ((s_negmask[j >> 5] >> (j & 31)) & 1) {
                float x = row[j];
                if (fkey(x) > t) { cg++; se += expf(x); }
            }
        cg = blockReduceInt(cg, &s_red);
        float tot = blockReduceFloat(se, s_warp);
        if (tid == 0) s_Eh = tot + (float)(NEGN - cg) * expf(unfkey(t));
        __syncthreads();
    }
    if (!okR) {
        u64 t = s_thrR;
        float se = 0.f;
        for (int j = tid; j < BR; j += 512)
            if ((s_negmask[j >> 5] >> (j & 31)) & 1) {
                u64 w = ((u64)__float_as_uint(rrow[j]) << 32) | (unsigned)j;
                if (w <= t) se += expf(row[j]);
            }
        float tot = blockReduceFloat(se, s_warp);
        if (tid == 0) s_Er = tot;
        __syncthreads();
    }

    // ---- per-row loss: 128 smallest pos values (with ties) ------------------
    const float Eh = s_Eh, Er = s_Er;
    const uint32_t tP = s_thrP;
    int c = 0; double ts = 0.0;
    for (int i = tid; i < MEMSZ; i += 512) {
        float pv = s_pos[i];
        if (fkey(pv) < tP) { c++; ts += lterm(pv, Eh, Er); }
    }
    c = blockReduceInt(c, &s_red);
    double tsum = blockReduceDouble(ts, s_warpd);
    if (tid == 0) {
        tsum += (double)(POSN - c) * lterm(unfkey(tP), Eh, Er);
        atomicAdd(&g_loss, tsum);
    }
}

__global__ void finalize_kernel(float* out) {
    out[0] = (float)(g_loss / (double)(BATCH * 2 * POSN));
}

// ------------------------- launcher -----------------------------------------
extern "C" void kernel_launch(void* const* d_in, const int* in_sizes, int n_in,
                              void* d_out, int out_size) {
    const float* f    = (const float*)d_in[0];
    const int*   lab  = (const int*)d_in[1];
    const int*   eidx = (const int*)d_in[2];
    const float* bank = (const float*)d_in[3];
    const float* flag = (const float*)d_in[4];
    const float* rnd  = (const float*)d_in[5];
    float* out = (float*)d_out;

    const int GEMM_SMEM = 2 * 2 * GBM * GPAD * 4;   // 73728 bytes
    cudaFuncSetAttribute(gemm_tf32_kernel,
                         cudaFuncAttributeMaxDynamicSharedMemorySize, GEMM_SMEM);

    prep_kernel<<<6, 256>>>(flag);
    scatter_kernel<<<2, 256>>>(eidx);
    gemm_tf32_kernel<<<dim3((BR + GBN - 1) / GBN, BATCH / GBM), 128, GEMM_SMEM>>>(f, bank);
    fixup_kernel<<<BATCH, 256>>>(f, eidx);
    negsel_kernel<<<BATCH, 512>>>(lab, rnd);
    finalize_kernel<<<1, 1>>>(out);
    (void)in_sizes; (void)n_in; (void)out_size;
}

// round 6
// speedup vs baseline: 3.9492x; 2.0159x over previous
#include <cuda_runtime.h>
#include <math.h>
#include <stdint.h>

#define BATCH 512
#define CH    256
#define CLS   60
#define MEMSZ 684
#define BR    41040
#define POSN  128
#define NEGN  512
#define NWORDS 1283          // ceil(BR/32)
#define CAPN  2048
#define NQ    (BR/4)         // 10260 float4 per row

typedef unsigned long long u64;

// ------------------------- device scratch -----------------------------------
__device__ float    g_pairs[(size_t)BATCH * BR];   // 84 MB
__device__ uint32_t g_validbits[NWORDS];
__device__ uint32_t g_eqtab[CLS * 15];
__device__ double   g_loss;

// ------------------------- prep ---------------------------------------------
__global__ void prep_kernel(const float* __restrict__ flag) {
    int i = blockIdx.x * blockDim.x + threadIdx.x;
    if (i == 0) g_loss = 0.0;
    if (i < CLS * 15) {
        int lbl = i / 15, p = i % 15;
        int off = (32 * p) % 60;
        uint32_t m = 0;
        for (int b = 0; b < 32; b++) if ((off + b) % 60 == lbl) m |= 1u << b;
        g_eqtab[i] = m;
    }
    if (i < NWORDS) {
        uint32_t m = 0; int base = i * 32;
        for (int b = 0; b < 32; b++) {
            int j = base + b;
            if (j < BR && flag[j] > 0.f) m |= 1u << b;
        }
        g_validbits[i] = m;
    }
}

__global__ void scatter_kernel(const int* __restrict__ eidx) {
    int m = blockIdx.x * blockDim.x + threadIdx.x;
    if (m < BATCH) { int j = eidx[m]; atomicOr(&g_validbits[j >> 5], 1u << (j & 31)); }
}

// ------------------------- tf32 tensor-core GEMM ----------------------------
#define GBM 128
#define GBN 128
#define GBK 32
#define GPAD 36
#define GKITERS 8

__device__ __forceinline__ void mma_tf32(float* c, const uint32_t* a, const uint32_t* b) {
    asm volatile(
        "mma.sync.aligned.m16n8k8.row.col.f32.tf32.tf32.f32 "
        "{%0,%1,%2,%3},{%4,%5,%6,%7},{%8,%9},{%0,%1,%2,%3};"
        : "+f"(c[0]), "+f"(c[1]), "+f"(c[2]), "+f"(c[3])
        : "r"(a[0]), "r"(a[1]), "r"(a[2]), "r"(a[3]), "r"(b[0]), "r"(b[1]));
}

__global__ __launch_bounds__(128) void gemm_tf32_kernel(const float* __restrict__ F,
                                                        const float* __restrict__ BK_) {
    extern __shared__ float sm[];
    float* As = sm;
    float* Bs = sm + 2 * GBM * GPAD;
#define ASM(bf, r, c) As[(bf) * GBM * GPAD + (r) * GPAD + (c)]
#define BSM(bf, r, c) Bs[(bf) * GBM * GPAD + (r) * GPAD + (c)]

    const int bj = blockIdx.x * GBN;
    const int bn = blockIdx.y * GBM;
    const int tid = threadIdx.x;
    const int wid = tid >> 5, lane = tid & 31;
    const int wm = (wid >> 1) * 64, wn = (wid & 1) * 64;
    const int tr = lane >> 2, tc = lane & 3;

    float acc[4][8][4];
#pragma unroll
    for (int i = 0; i < 4; i++)
#pragma unroll
        for (int j = 0; j < 8; j++)
#pragma unroll
            for (int k = 0; k < 4; k++) acc[i][j][k] = 0.f;

    auto load_stage = [&](int buf, int kt) {
        int k0 = kt * GBK;
#pragma unroll
        for (int i = 0; i < 8; i++) {
            int slot = tid + i * 128;
            int r = slot >> 3;
            int kq = (slot & 7) * 4;
            uint32_t da = (uint32_t)__cvta_generic_to_shared(&ASM(buf, r, kq));
            const float* ga = F + (size_t)(bn + r) * CH + k0 + kq;
            asm volatile("cp.async.cg.shared.global [%0], [%1], 16;" :: "r"(da), "l"(ga));
            int j = bj + r;
            int ok = (j < BR) ? 16 : 0;
            const float* gb = BK_ + (size_t)(j < BR ? j : 0) * CH + k0 + kq;
            uint32_t db = (uint32_t)__cvta_generic_to_shared(&BSM(buf, r, kq));
            asm volatile("cp.async.cg.shared.global [%0], [%1], 16, %2;" :: "r"(db), "l"(gb), "r"(ok));
        }
    };

    load_stage(0, 0);
    asm volatile("cp.async.commit_group;");

    for (int kt = 0; kt < GKITERS; kt++) {
        asm volatile("cp.async.wait_group 0;");
        __syncthreads();
        if (kt + 1 < GKITERS) {
            load_stage((kt + 1) & 1, kt + 1);
            asm volatile("cp.async.commit_group;");
        }
        int b = kt & 1;
#pragma unroll
        for (int ks = 0; ks < 4; ks++) {
            int kk = ks * 8;
            uint32_t af[4][4], bf[8][2];
#pragma unroll
            for (int mi = 0; mi < 4; mi++) {
                int r0 = wm + mi * 16 + tr;
                af[mi][0] = __float_as_uint(ASM(b, r0,     kk + tc));
                af[mi][1] = __float_as_uint(ASM(b, r0 + 8, kk + tc));
                af[mi][2] = __float_as_uint(ASM(b, r0,     kk + tc + 4));
                af[mi][3] = __float_as_uint(ASM(b, r0 + 8, kk + tc + 4));
            }
#pragma unroll
            for (int ni = 0; ni < 8; ni++) {
                int r0 = wn + ni * 8 + tr;
                bf[ni][0] = __float_as_uint(BSM(b, r0, kk + tc));
                bf[ni][1] = __float_as_uint(BSM(b, r0, kk + tc + 4));
            }
#pragma unroll
            for (int mi = 0; mi < 4; mi++)
#pragma unroll
                for (int ni = 0; ni < 8; ni++) mma_tf32(acc[mi][ni], af[mi], bf[ni]);
        }
    }

#pragma unroll
    for (int mi = 0; mi < 4; mi++) {
        int m = bn + wm + mi * 16 + tr;
        float* p0 = &g_pairs[(size_t)m * BR];
        float* p1 = &g_pairs[(size_t)(m + 8) * BR];
#pragma unroll
        for (int ni = 0; ni < 8; ni++) {
            int col = bj + wn + ni * 8 + tc * 2;
            if (col < BR) {
                *(float2*)(p0 + col) = make_float2(acc[mi][ni][0], acc[mi][ni][1]);
                *(float2*)(p1 + col) = make_float2(acc[mi][ni][2], acc[mi][ni][3]);
            }
        }
    }
#undef ASM
#undef BSM
}

// -------- fixup: S = F @ F^T (fp32, tiled), scatter to enqueued columns -----
__global__ __launch_bounds__(256) void fixup_gemm_kernel(const float* __restrict__ F,
                                                         const int* __restrict__ eidx) {
    __shared__ float As[64][33];
    __shared__ float Bs[64][33];
    __shared__ int   s_col[64];
    const int bj = blockIdx.x * 64;   // m (enqueue slot) base
    const int bn = blockIdx.y * 64;   // n (batch row) base
    const int tid = threadIdx.x;
    const int tx = tid & 15, ty = tid >> 4;
    if (tid < 64) s_col[tid] = eidx[bj + tid];
    float acc[4][4] = {};

    for (int k0 = 0; k0 < CH; k0 += 32) {
#pragma unroll
        for (int l = 0; l < 2; l++) {
            int idx = tid + l * 256;
            int r = idx >> 3;
            int c = (idx & 7) << 2;
            float4 v = *(const float4*)&F[(size_t)(bn + r) * CH + k0 + c];
            As[r][c] = v.x; As[r][c + 1] = v.y; As[r][c + 2] = v.z; As[r][c + 3] = v.w;
            float4 w = *(const float4*)&F[(size_t)(bj + r) * CH + k0 + c];
            Bs[r][c] = w.x; Bs[r][c + 1] = w.y; Bs[r][c + 2] = w.z; Bs[r][c + 3] = w.w;
        }
        __syncthreads();
#pragma unroll
        for (int kk = 0; kk < 32; kk++) {
            float a[4], b[4];
#pragma unroll
            for (int i = 0; i < 4; i++) a[i] = As[ty * 4 + i][kk];
#pragma unroll
            for (int j = 0; j < 4; j++) b[j] = Bs[tx * 4 + j][kk];
#pragma unroll
            for (int i = 0; i < 4; i++)
#pragma unroll
                for (int j = 0; j < 4; j++) acc[i][j] += a[i] * b[j];
        }
        __syncthreads();
    }
#pragma unroll
    for (int i = 0; i < 4; i++) {
        int nrow = bn + ty * 4 + i;
#pragma unroll
        for (int j = 0; j < 4; j++)
            g_pairs[(size_t)nrow * BR + s_col[tx * 4 + j]] = acc[i][j];
    }
}

// ------------------------- helpers ------------------------------------------
__device__ __forceinline__ uint32_t fkey(float v) {
    uint32_t u = __float_as_uint(v);
    return (u & 0x80000000u) ? ~u : (u | 0x80000000u);
}
__device__ __forceinline__ float unfkey(uint32_t u) {
    uint32_t b = (u & 0x80000000u) ? (u & 0x7FFFFFFFu) : ~u;
    return __uint_as_float(b);
}

__device__ __forceinline__ int warpRedInt(int c) {
#pragma unroll
    for (int o = 16; o > 0; o >>= 1) c += __shfl_xor_sync(0xffffffffu, c, o);
    return c;
}
__device__ __forceinline__ float warpRedF(float v) {
#pragma unroll
    for (int o = 16; o > 0; o >>= 1) v += __shfl_xor_sync(0xffffffffu, v, o);
    return v;
}

// warp-private rank selection (shfl-only, no block syncs)
__device__ uint32_t warp_sel_largest_u32(const uint32_t* a, int len, int need) {
    int lane = threadIdx.x & 31;
    uint32_t lo = 0, hi = 0xFFFFFFFFu;
    while (lo < hi) {
        uint32_t d = hi - lo;
        uint32_t mid = lo + (d >> 1) + (d & 1);
        int c = 0;
        for (int i = lane; i < len; i += 32) c += (a[i] >= mid);
        c = warpRedInt(c);
        if (c >= need) lo = mid; else hi = mid - 1;
    }
    return lo;
}
__device__ uint32_t warp_sel_smallest_u32(const uint32_t* a, int len, int need) {
    int lane = threadIdx.x & 31;
    uint32_t lo = 0, hi = 0xFFFFFFFFu;
    while (lo < hi) {
        uint32_t mid = lo + ((hi - lo) >> 1);
        int c = 0;
        for (int i = lane; i < len; i += 32) c += (a[i] <= mid);
        c = warpRedInt(c);
        if (c >= need) hi = mid; else lo = mid + 1;
    }
    return lo;
}
__device__ u64 warp_sel_smallest_u64(const u64* a, int len, int need) {
    int lane = threadIdx.x & 31;
    u64 lo = 0ull, hi = 0xFFFFFFFFFFFFFFFFull;
    while (lo < hi) {
        u64 mid = lo + ((hi - lo) >> 1);
        int c = 0;
        for (int i = lane; i < len; i += 32) c += (a[i] <= mid);
        c = warpRedInt(c);
        if (c >= need) hi = mid; else lo = mid + 1;
    }
    return lo;
}
__device__ uint32_t warp_sel_smallest_fkey(const float* a, int len, int need) {
    int lane = threadIdx.x & 31;
    uint32_t lo = 0, hi = 0xFFFFFFFFu;
    while (lo < hi) {
        uint32_t mid = lo + ((hi - lo) >> 1);
        int c = 0;
        for (int i = lane; i < len; i += 32) c += (fkey(a[i]) <= mid);
        c = warpRedInt(c);
        if (c >= need) hi = mid; else lo = mid + 1;
    }
    return lo;
}

__device__ __forceinline__ int blockReduceInt(int c, int* s_red) {
    __syncthreads();
    if (threadIdx.x == 0) *s_red = 0;
    __syncthreads();
    c = warpRedInt(c);
    if ((threadIdx.x & 31) == 0) atomicAdd(s_red, c);
    __syncthreads();
    return *s_red;
}
__device__ __forceinline__ float blockReduceFloat(float v, float* warpBuf) {
    v = warpRedF(v);
    int lane = threadIdx.x & 31, w = threadIdx.x >> 5;
    if (lane == 0) warpBuf[w] = v;
    __syncthreads();
    float s = 0.f;
    if (threadIdx.x == 0)
        for (int i = 0; i < (int)(blockDim.x >> 5); i++) s += warpBuf[i];
    __syncthreads();
    return s;   // thread 0 only
}
__device__ __forceinline__ double blockReduceDouble(double v, double* warpBuf) {
#pragma unroll
    for (int o = 16; o > 0; o >>= 1) v += __shfl_xor_sync(0xffffffffu, v, o);
    int lane = threadIdx.x & 31, w = threadIdx.x >> 5;
    if (lane == 0) warpBuf[w] = v;
    __syncthreads();
    double s = 0.0;
    if (threadIdx.x == 0)
        for (int i = 0; i < (int)(blockDim.x >> 5); i++) s += warpBuf[i];
    __syncthreads();
    return s;   // thread 0 only
}

__device__ __forceinline__ double lterm(float pv, float Eh, float Er) {
    float e = expf(pv);
    return (double)(logf(e + Eh) - pv) + (double)(logf(e + Er) - pv);
}

// ------- fused: hard top-512 + rand 512 + pos-128 + per-row loss ------------
__global__ __launch_bounds__(512) void negsel_kernel(const int* __restrict__ label,
                                                     const float* __restrict__ rnd) {
    __shared__ uint32_t s_negmask[NWORDS];
    __shared__ uint32_t s_posmask[NWORDS];
    __shared__ uint32_t s_listH[CAPN];
    __shared__ u64      s_listR[CAPN];
    __shared__ uint32_t s_sampH[1024];
    __shared__ uint32_t s_sampR[1024];
    __shared__ float    s_pos[MEMSZ];
    __shared__ int      s_cntH, s_cntR, s_red;
    __shared__ float    s_warp[16];
    __shared__ double   s_warpd[16];
    __shared__ uint32_t s_thrH, s_thrP, s_thrRs;
    __shared__ u64      s_thrR;
    __shared__ float    s_Eh, s_Er;

    const int n = blockIdx.x;
    const int lbl = label[n];
    const float* row  = g_pairs + (size_t)n * BR;
    const float* rrow = rnd + (size_t)n * BR;
    const int tid = threadIdx.x, wid = tid >> 5, lane = tid & 31;

    for (int w = tid; w < NWORDS; w += 512) {
        uint32_t v = g_validbits[w], e = g_eqtab[lbl * 15 + (w % 15)];
        s_negmask[w] = v & ~e;
        s_posmask[w] = v & e;
    }
    for (int i = tid; i < MEMSZ; i += 512) s_pos[i] = INFINITY;
    if (tid == 0) { s_cntH = 0; s_cntR = 0; }
    __syncthreads();

    // ---- 1024 deterministic samples each for hard & rand -------------------
    for (int s = tid; s < 1024; s += 512) {
        int j = 37 * s + 11;
        bool ok = (s_negmask[j >> 5] >> (j & 31)) & 1;
        s_sampH[s] = ok ? fkey(row[j]) : 0u;                     // -inf key
        s_sampR[s] = ok ? __float_as_uint(rrow[j]) : 0xFFFFFFFFu; // huge key
    }
    __syncthreads();
    if (wid == 0) { uint32_t t = warp_sel_largest_u32(s_sampH, 1024, 32);
                    if (lane == 0) s_thrH = t; }
    if (wid == 1) { uint32_t t = warp_sel_smallest_u32(s_sampR, 1024, 32);
                    if (lane == 0) s_thrRs = t; }
    __syncthreads();
    const float thrHs = unfkey(s_thrH);
    const float thrRs = __uint_as_float(s_thrRs);

    // ---- single fused scan --------------------------------------------------
    for (int q = tid; q < NQ; q += 512) {
        uint32_t nm = (s_negmask[q >> 3] >> ((q & 7) << 2)) & 0xF;
        uint32_t pm = (s_posmask[q >> 3] >> ((q & 7) << 2)) & 0xF;
        if (!(nm | pm)) continue;
        float4 v = ((const float4*)row)[q];
        float vv[4] = {v.x, v.y, v.z, v.w};
        int j0 = q << 2;
        if (pm) {
#pragma unroll
            for (int e = 0; e < 4; e++)
                if ((pm >> e) & 1)
                    s_pos[(unsigned)(j0 + e - lbl) / 60u] = vv[e];
        }
        if (nm) {
            float4 r = ((const float4*)rrow)[q];
            float rr[4] = {r.x, r.y, r.z, r.w};
#pragma unroll
            for (int e = 0; e < 4; e++) {
                if ((nm >> e) & 1) {
                    if (vv[e] >= thrHs) {
                        int p = atomicAdd(&s_cntH, 1);
                        if (p < CAPN) s_listH[p] = fkey(vv[e]);
                    }
                    if (rr[e] <= thrRs) {
                        int p = atomicAdd(&s_cntR, 1);
                        if (p < CAPN)
                            s_listR[p] = ((u64)__float_as_uint(rr[e]) << 32) |
                                         (unsigned)(j0 + e);
                    }
                }
            }
        }
    }
    __syncthreads();
    const int cntH = s_cntH, cntR = s_cntR;
    const bool okH = (cntH >= NEGN && cntH <= CAPN);
    const bool okR = (cntR >= NEGN && cntR <= CAPN);

    // ---- thresholds: warps 0/1/2 in parallel (shfl-only) --------------------
    if (okH && wid == 0) { uint32_t t = warp_sel_largest_u32(s_listH, cntH, NEGN);
                           if (lane == 0) s_thrH = t; }
    if (okR && wid == 1) { u64 t = warp_sel_smallest_u64(s_listR, cntR, NEGN);
                           if (lane == 0) s_thrR = t; }
    if (wid == 2) { uint32_t t = warp_sel_smallest_fkey(s_pos, MEMSZ, POSN);
                    if (lane == 0) s_thrP = t; }
    __syncthreads();

    // ---- rare fallbacks: block-wide bisect over gmem ------------------------
    if (!okH) {
        uint32_t lo = 0, hi = 0xFFFFFFFFu;
        while (lo < hi) {
            uint32_t d = hi - lo;
            uint32_t mid = lo + (d >> 1) + (d & 1);
            int c = 0;
            for (int j = tid; j < BR; j += 512)
                if ((s_negmask[j >> 5] >> (j & 31)) & 1) c += (fkey(row[j]) >= mid);
            c = blockReduceInt(c, &s_red);
            if (c >= NEGN) lo = mid; else hi = mid - 1;
        }
        if (tid == 0) s_thrH = lo;
        __syncthreads();
    }
    if (!okR) {
        u64 lo = 0ull, hi = 0xFFFFFFFFFFFFFFFFull;
        while (lo < hi) {
            u64 mid = lo + ((hi - lo) >> 1);
            int c = 0;
            for (int j = tid; j < BR; j += 512)
                if ((s_negmask[j >> 5] >> (j & 31)) & 1) {
                    u64 w = ((u64)__float_as_uint(rrow[j]) << 32) | (unsigned)j;
                    c += (w <= mid);
                }
            c = blockReduceInt(c, &s_red);
            if (c >= NEGN) hi = mid; else lo = mid + 1;
        }
        if (tid == 0) s_thrR = lo;
        __syncthreads();
    }

    // ---- Eh / Er sums -------------------------------------------------------
    if (okH && wid == 0) {
        uint32_t t = s_thrH;
        int cg = 0; float se = 0.f;
        for (int i = lane; i < cntH; i += 32) {
            uint32_t u = s_listH[i];
            if (u > t) { cg++; se += expf(unfkey(u)); }
        }
        cg = warpRedInt(cg); se = warpRedF(se);
        if (lane == 0) s_Eh = se + (float)(NEGN - cg) * expf(unfkey(t));
    }
    if (okR && wid == 1) {
        u64 t = s_thrR;
        float se = 0.f;
        for (int i = lane; i < cntR; i += 32) {
            u64 w = s_listR[i];
            if (w <= t) se += expf(row[(unsigned)(w & 0xFFFFFFFFull)]);
        }
        se = warpRedF(se);
        if (lane == 0) s_Er = se;
    }
    __syncthreads();
    if (!okH) {
        uint32_t t = s_thrH;
        int cg = 0; float se = 0.f;
        for (int j = tid; j < BR; j += 512)
            if ((s_negmask[j >> 5] >> (j & 31)) & 1) {
                float x = row[j];
                if (fkey(x) > t) { cg++; se += expf(x); }
            }
        cg = blockReduceInt(cg, &s_red);
        float tot = blockReduceFloat(se, s_warp);
        if (tid == 0) s_Eh = tot + (float)(NEGN - cg) * expf(unfkey(t));
        __syncthreads();
    }
    if (!okR) {
        u64 t = s_thrR;
        float se = 0.f;
        for (int j = tid; j < BR; j += 512)
            if ((s_negmask[j >> 5] >> (j & 31)) & 1) {
                u64 w = ((u64)__float_as_uint(rrow[j]) << 32) | (unsigned)j;
                if (w <= t) se += expf(row[j]);
            }
        float tot = blockReduceFloat(se, s_warp);
        if (tid == 0) s_Er = tot;
        __syncthreads();
    }

    // ---- per-row loss: 128 smallest pos values (with ties) ------------------
    const float Eh = s_Eh, Er = s_Er;
    const uint32_t tP = s_thrP;
    int c = 0; double ts = 0.0;
    for (int i = tid; i < MEMSZ; i += 512) {
        float pv = s_pos[i];
        if (fkey(pv) < tP) { c++; ts += lterm(pv, Eh, Er); }
    }
    c = blockReduceInt(c, &s_red);
    double tsum = blockReduceDouble(ts, s_warpd);
    if (tid == 0) {
        tsum += (double)(POSN - c) * lterm(unfkey(tP), Eh, Er);
        atomicAdd(&g_loss, tsum);
    }
}

__global__ void finalize_kernel(float* out) {
    out[0] = (float)(g_loss / (double)(BATCH * 2 * POSN));
}

// ------------------------- launcher -----------------------------------------
extern "C" void kernel_launch(void* const* d_in, const int* in_sizes, int n_in,
                              void* d_out, int out_size) {
    const float* f    = (const float*)d_in[0];
    const int*   lab  = (const int*)d_in[1];
    const int*   eidx = (const int*)d_in[2];
    const float* bank = (const float*)d_in[3];
    const float* flag = (const float*)d_in[4];
    const float* rnd  = (const float*)d_in[5];
    float* out = (float*)d_out;

    const int GEMM_SMEM = 2 * 2 * GBM * GPAD * 4;   // 73728 bytes
    cudaFuncSetAttribute(gemm_tf32_kernel,
                         cudaFuncAttributeMaxDynamicSharedMemorySize, GEMM_SMEM);

    prep_kernel<<<6, 256>>>(flag);
    scatter_kernel<<<2, 256>>>(eidx);
    gemm_tf32_kernel<<<dim3((BR + GBN - 1) / GBN, BATCH / GBM), 128, GEMM_SMEM>>>(f, bank);
    fixup_gemm_kernel<<<dim3(BATCH / 64, BATCH / 64), 256>>>(f, eidx);
    negsel_kernel<<<BATCH, 512>>>(lab, rnd);
    finalize_kernel<<<1, 1>>>(out);
    (void)in_sizes; (void)n_in; (void)out_size;
}